// round 2
// baseline (speedup 1.0000x reference)
#include <cuda_runtime.h>
#include <math.h>
#include <float.h>

#define NODES 10242
#define NG    16380
#define LATN  91
#define LONN  180
#define CH    64
#define BATCH 4
#define KNN_K 8

// Scratch (no cudaMalloc allowed)
__device__ float4 g_vert4[NODES];      // {x, y, z, m2}
__device__ float  g_knw[NG * KNN_K];
__device__ int    g_kni[NG * KNN_K];

// ---------------------------------------------------------------------------
// Prep: pack vertices as {x,y,z, m2} with m2 = (x*x + y*y) + z*z rounded
// exactly like the reference's elementwise-square + sequential reduce.
// ---------------------------------------------------------------------------
__global__ void prep_kernel(const float* __restrict__ mv) {
    int i = blockIdx.x * 256 + threadIdx.x;
    if (i < NODES) {
        float x = mv[3*i], y = mv[3*i+1], z = mv[3*i+2];
        float m2 = __fadd_rn(__fadd_rn(__fmul_rn(x,x), __fmul_rn(y,y)), __fmul_rn(z,z));
        g_vert4[i] = make_float4(x, y, z, m2);
    }
}

// ---------------------------------------------------------------------------
// KNN: one warp handles 4 grid points; lanes stride the vertex list (staged
// through smem in 32KB chunks). Ranking value is the reference's exact d2:
//   dot = fmaf(gz,mz, fmaf(gy,my, fmul(gx,mx)))        (ascending-k chain)
//   d2  = fsub(fadd(g2, m2), fmul(2, dot))
// so selection agrees bit-for-bit with the reference's top_k ordering.
// ---------------------------------------------------------------------------
#define VC  2048   // vertices per smem chunk (float4 -> 32KB)
#define GPW 4      // grid points per warp

__global__ __launch_bounds__(256) void knn_kernel(const float* __restrict__ lat,
                                                  const float* __restrict__ lon) {
    __shared__ float4 sv[VC];
    const int lane  = threadIdx.x & 31;
    const int warp  = threadIdx.x >> 5;
    const int gbase = blockIdx.x * (8 * GPW) + warp * GPW;

    float gx[GPW], gy[GPW], gz[GPW], g2[GPW];
#pragma unroll
    for (int u = 0; u < GPW; ++u) {
        int g = gbase + u; if (g >= NG) g = NG - 1;  // clamp (no store later)
        float la = lat[g / LONN];
        float lo = lon[g % LONN];
        float cl = cosf(la);
        float x = __fmul_rn(cl, cosf(lo));
        float y = __fmul_rn(cl, sinf(lo));
        float z = sinf(la);
        gx[u] = x; gy[u] = y; gz[u] = z;
        g2[u] = __fadd_rn(__fadd_rn(__fmul_rn(x,x), __fmul_rn(y,y)), __fmul_rn(z,z));
    }

    float dd[GPW][8];   // sorted ascending d2
    int   xi[GPW][8];
#pragma unroll
    for (int u = 0; u < GPW; ++u)
#pragma unroll
        for (int j = 0; j < 8; ++j) { dd[u][j] = FLT_MAX; xi[u][j] = 0; }

    for (int base = 0; base < NODES; base += VC) {
        int n = NODES - base; if (n > VC) n = VC;
        __syncthreads();
        for (int i = threadIdx.x; i < n; i += 256) sv[i] = g_vert4[base + i];
        __syncthreads();

        for (int v = lane; v < n; v += 32) {
            float4 p = sv[v];
            int vi = base + v;
#pragma unroll
            for (int u = 0; u < GPW; ++u) {
                float dot = __fmaf_rn(gz[u], p.z,
                            __fmaf_rn(gy[u], p.y,
                            __fmul_rn(gx[u], p.x)));
                float d2  = __fsub_rn(__fadd_rn(g2[u], p.w), __fmul_rn(2.0f, dot));
                if (d2 < dd[u][7]) {
                    dd[u][7] = d2; xi[u][7] = vi;
#pragma unroll
                    for (int j = 7; j > 0; --j) {
                        if (dd[u][j] < dd[u][j-1]) {
                            float td = dd[u][j]; dd[u][j] = dd[u][j-1]; dd[u][j-1] = td;
                            int   ti = xi[u][j]; xi[u][j] = xi[u][j-1]; xi[u][j-1] = ti;
                        }
                    }
                }
            }
        }
    }

#pragma unroll
    for (int u = 0; u < GPW; ++u) {
        float myd = 0.f; int myi = 0;   // lane r captures rank-r result
#pragma unroll
        for (int r = 0; r < 8; ++r) {
            float bv = dd[u][0]; int bi = xi[u][0]; int bl = lane;
#pragma unroll
            for (int off = 16; off > 0; off >>= 1) {
                float ov = __shfl_down_sync(0xffffffffu, bv, off);
                int   oi = __shfl_down_sync(0xffffffffu, bi, off);
                int   ol = __shfl_down_sync(0xffffffffu, bl, off);
                if (ov < bv) { bv = ov; bi = oi; bl = ol; }
            }
            bv = __shfl_sync(0xffffffffu, bv, 0);
            bi = __shfl_sync(0xffffffffu, bi, 0);
            bl = __shfl_sync(0xffffffffu, bl, 0);
            if (lane == bl) {  // winner pops its head
#pragma unroll
                for (int j = 0; j < 7; ++j) { dd[u][j] = dd[u][j+1]; xi[u][j] = xi[u][j+1]; }
                dd[u][7] = FLT_MAX;
            }
            if (lane == r) { myd = bv; myi = bi; }
        }
        // softmax over -dist among the 8 (lanes 0..7); rank0 = nearest
        float dist = sqrtf(fmaxf(myd, 1e-12f));
        float dmin = __shfl_sync(0xffffffffu, dist, 0);
        float w = 0.f;
        if (lane < 8) w = expf(__fsub_rn(dmin, dist));
        float s = w;
#pragma unroll
        for (int off = 16; off > 0; off >>= 1) s += __shfl_xor_sync(0xffffffffu, s, off);
        int g = gbase + u;
        if (lane < 8 && g < NG) {
            g_knw[g * 8 + lane] = __fdiv_rn(w, s);
            g_kni[g * 8 + lane] = myi;
        }
    }
}

// ---------------------------------------------------------------------------
// Gather + weighted combine + 64x64 linear + NCHW store.
// Block = 8 consecutive grid points, 256 threads = (b, c).
// ---------------------------------------------------------------------------
__global__ __launch_bounds__(256) void gather_kernel(const float* __restrict__ M,
                                                     const float* __restrict__ W,
                                                     const float* __restrict__ bias,
                                                     float* __restrict__ out) {
    __shared__ float s_w[8][8];
    __shared__ int   s_i[8][8];
    __shared__ float s_W[64 * 65];                       // s_W[c*65+c'] = W[c'][c]
    __shared__ __align__(16) float s_it[BATCH * CH * 8]; // [b][c][g], pitch 8

    const int tid = threadIdx.x;
    const int g0  = blockIdx.x * 8;

    for (int i = tid; i < CH * CH; i += 256) {
        int cp = i >> 6;          // c'
        int c  = i & 63;          // c
        s_W[c * 65 + cp] = W[i];  // stride-65 writes: conflict-free
    }
    if (tid < 64) {
        int gg = tid >> 3, k = tid & 7;
        int g = g0 + gg;
        if (g < NG) { s_w[gg][k] = g_knw[g * 8 + k]; s_i[gg][k] = g_kni[g * 8 + k]; }
        else        { s_w[gg][k] = 0.f;              s_i[gg][k] = 0; }
    }
    __syncthreads();

    const int b = tid >> 6;
    const int c = tid & 63;

    // Phase 1: gather + weighted sum (8 independent loads per g -> good MLP)
    const float* Mb = M + (size_t)b * NODES * CH + c;
    float r[8];
#pragma unroll
    for (int gg = 0; gg < 8; ++gg) {
        float a = 0.f;
#pragma unroll
        for (int k = 0; k < 8; ++k)
            a = __fmaf_rn(s_w[gg][k], Mb[(size_t)s_i[gg][k] * CH], a);
        r[gg] = a;
    }
    float* ip = &s_it[(b * CH + c) * 8];
    ((float4*)ip)[0] = make_float4(r[0], r[1], r[2], r[3]);
    ((float4*)ip)[1] = make_float4(r[4], r[5], r[6], r[7]);
    __syncthreads();

    // Phase 2: linear over channels, register-blocked over the 8 g's
    float a[8];
    const float bv = bias[c];
#pragma unroll
    for (int gg = 0; gg < 8; ++gg) a[gg] = bv;
    const float* ib = &s_it[b * CH * 8];
#pragma unroll 8
    for (int cc = 0; cc < CH; ++cc) {
        float4 v0 = ((const float4*)(ib + cc * 8))[0];  // warp-broadcast
        float4 v1 = ((const float4*)(ib + cc * 8))[1];
        float w = s_W[cc * 65 + c];                     // conflict-free
        a[0] = __fmaf_rn(w, v0.x, a[0]); a[1] = __fmaf_rn(w, v0.y, a[1]);
        a[2] = __fmaf_rn(w, v0.z, a[2]); a[3] = __fmaf_rn(w, v0.w, a[3]);
        a[4] = __fmaf_rn(w, v1.x, a[4]); a[5] = __fmaf_rn(w, v1.y, a[5]);
        a[6] = __fmaf_rn(w, v1.z, a[6]); a[7] = __fmaf_rn(w, v1.w, a[7]);
    }

    // Store: out[b][c'][lat][lon], g contiguous -> each thread owns a 32B run
    float* op = out + (size_t)(b * CH + c) * NG + g0;
    if (g0 + 8 <= NG) {
        ((float4*)op)[0] = make_float4(a[0], a[1], a[2], a[3]);
        ((float4*)op)[1] = make_float4(a[4], a[5], a[6], a[7]);
    } else {
#pragma unroll
        for (int gg = 0; gg < 8; ++gg)
            if (g0 + gg < NG) op[gg] = a[gg];
    }
}

// ---------------------------------------------------------------------------
extern "C" void kernel_launch(void* const* d_in, const int* in_sizes, int n_in,
                              void* d_out, int out_size) {
    const float* mesh_output   = (const float*)d_in[0];  // (4,10242,64)
    const float* mesh_vertices = (const float*)d_in[1];  // (10242,3)
    const float* lat           = (const float*)d_in[2];  // (91,)
    const float* lon           = (const float*)d_in[3];  // (180,)
    const float* W             = (const float*)d_in[4];  // (64,64)
    const float* bvec          = (const float*)d_in[5];  // (64,)
    float* out = (float*)d_out;                          // (4,64,91,180)

    prep_kernel<<<(NODES + 255) / 256, 256>>>(mesh_vertices);
    knn_kernel<<<(NG + 8 * GPW - 1) / (8 * GPW), 256>>>(lat, lon);
    gather_kernel<<<(NG + 7) / 8, 256>>>(mesh_output, W, bvec, out);
}

// round 4
// speedup vs baseline: 2.5374x; 2.5374x over previous
#include <cuda_runtime.h>
#include <math.h>
#include <float.h>

#define NODES 10242
#define NG    16380
#define LATN  91
#define LONN  180
#define CH    64
#define BATCH 4

#define NBINS 128
#define BINW  (2.0f / NBINS)

// Scratch (no cudaMalloc allowed)
__device__ float4 g_xyzm[NODES];        // {x,y,z,m2} original order
__device__ int    g_binCnt[NBINS];
__device__ int    g_binStart[NBINS + 1];
__device__ int    g_binCur[NBINS];
__device__ float4 g_sorted[NODES];      // z-binned
__device__ int    g_sidx[NODES];        // original index of sorted node
__device__ float  g_knw[NG * 8];
__device__ int    g_kni[NG * 8];

__device__ __forceinline__ int zbin(float z) {
    int b = (int)((z + 1.0f) * (NBINS * 0.5f));
    return min(max(b, 0), NBINS - 1);
}

// ---------------------------------------------------------------------------
__global__ void zero_kernel() {
    if (threadIdx.x < NBINS) g_binCnt[threadIdx.x] = 0;
}

// Pack {x,y,z,m2} with the reference's exact rounding; histogram z-bins.
__global__ void prep_hist_kernel(const float* __restrict__ mv) {
    int i = blockIdx.x * 256 + threadIdx.x;
    if (i < NODES) {
        float x = mv[3*i], y = mv[3*i+1], z = mv[3*i+2];
        float m2 = __fadd_rn(__fadd_rn(__fmul_rn(x,x), __fmul_rn(y,y)), __fmul_rn(z,z));
        g_xyzm[i] = make_float4(x, y, z, m2);
        atomicAdd(&g_binCnt[zbin(z)], 1);
    }
}

__global__ void scan_kernel() {
    if (threadIdx.x == 0) {
        int acc = 0;
        for (int k = 0; k < NBINS; ++k) {
            g_binStart[k] = acc;
            g_binCur[k]   = acc;
            acc += g_binCnt[k];
        }
        g_binStart[NBINS] = acc;
    }
}

__global__ void scatter_kernel() {
    int i = blockIdx.x * 256 + threadIdx.x;
    if (i < NODES) {
        float4 p = g_xyzm[i];
        int pos = atomicAdd(&g_binCur[zbin(p.z)], 1);
        g_sorted[pos] = p;
        g_sidx[pos]   = i;
    }
}

// ---------------------------------------------------------------------------
// KNN with z-band pruning. One block per half lat-row (90 lons); all threads
// share lat -> block-uniform z window. Expand bins outward from bin(z0);
// terminate when (dz to nearest unscanned bin edge)^2 > blockmax(worst8)+eps.
//
// Selection is STABLE top-k: lexicographic (d2, original_index), matching
// jax.lax.top_k's lowest-index tie-break. d2 is quantized at ~2.4e-7 by the
// (g2+m2) - 2*dot cancellation, so boundary ties DO occur (~8 expected over
// the grid); lex compare makes the selected set scan-order-invariant.
// ---------------------------------------------------------------------------
#define KT 96   // threads per knn block (3 warps), 90 active

__global__ __launch_bounds__(KT) void knn_kernel(const float* __restrict__ lat,
                                                 const float* __restrict__ lon) {
    __shared__ float4 s_nd[KT];
    __shared__ int    s_id[KT];
    __shared__ float  s_red[KT / 32];

    const int row  = blockIdx.x >> 1;
    const int half = blockIdx.x & 1;
    const int tid  = threadIdx.x;
    const bool active = (tid < 90);
    const int li   = half * 90 + (active ? tid : 0);   // lon index (clamped)

    const float la = lat[row];
    const float lo = lon[li];
    const float cl = cosf(la);
    const float x  = __fmul_rn(cl, cosf(lo));
    const float y  = __fmul_rn(cl, sinf(lo));
    const float z  = sinf(la);
    const float g2 = __fadd_rn(__fadd_rn(__fmul_rn(x,x), __fmul_rn(y,y)), __fmul_rn(z,z));

    float dd[8];  // sorted ascending by (d2, idx)
    int   xi[8];
#pragma unroll
    for (int j = 0; j < 8; ++j) { dd[j] = FLT_MAX; xi[j] = 0x7fffffff; }

    const float z0 = z;                  // block-uniform (same lat row)
    const int   b0 = zbin(z0);

    auto process_bin = [&](int bin) {
        const int s = g_binStart[bin];
        const int e = g_binStart[bin + 1];
        for (int base = s; base < e; base += KT) {     // block-uniform bounds
            const int n = min(KT, e - base);
            __syncthreads();
            if (tid < n) { s_nd[tid] = g_sorted[base + tid]; s_id[tid] = g_sidx[base + tid]; }
            __syncthreads();
            for (int j = 0; j < n; ++j) {
                float4 p = s_nd[j];                    // broadcast read
                int    id = s_id[j];
                float dot = __fmaf_rn(z, p.z,
                            __fmaf_rn(y, p.y,
                            __fmul_rn(x, p.x)));
                float d2  = __fsub_rn(__fadd_rn(g2, p.w), __fmul_rn(2.0f, dot));
                if (d2 < dd[7] || (d2 == dd[7] && id < xi[7])) {
                    dd[7] = d2; xi[7] = id;
#pragma unroll
                    for (int t = 7; t > 0; --t) {
                        if (dd[t] < dd[t-1] || (dd[t] == dd[t-1] && xi[t] < xi[t-1])) {
                            float td = dd[t]; dd[t] = dd[t-1]; dd[t-1] = td;
                            int   ti = xi[t]; xi[t] = xi[t-1]; xi[t-1] = ti;
                        }
                    }
                }
            }
        }
    };

    for (int r = 0; r < NBINS; ++r) {
        const int bl = b0 - r, br = b0 + r;
        if (bl < 0 && br >= NBINS) break;              // everything scanned
        if (bl >= 0) process_bin(bl);
        if (r > 0 && br < NBINS) process_bin(br);

        // distance from z0 to nearest UNSCANNED bin edge
        float dL = (bl > 0)         ? (z0 - (-1.0f + bl * BINW))       : FLT_MAX;
        float dR = (br < NBINS - 1) ? ((-1.0f + (br + 1) * BINW) - z0) : FLT_MAX;
        float dmin = fminf(dL, dR);
        if (dmin == FLT_MAX) break;                    // no unscanned bins remain

        // block-max of worst8 (idle threads run a clamped lon -> valid value)
        float w = dd[7];
#pragma unroll
        for (int off = 16; off > 0; off >>= 1)
            w = fmaxf(w, __shfl_xor_sync(0xffffffffu, w, off));
        __syncthreads();                               // protect s_red reuse
        if ((tid & 31) == 0) s_red[tid >> 5] = w;
        __syncthreads();
        float wm = s_red[0];
#pragma unroll
        for (int k = 1; k < KT / 32; ++k) wm = fmaxf(wm, s_red[k]);

        if (dmin * dmin > wm + 1e-5f) break;           // uniform decision
    }

    if (active) {
        float dist[8]; float dmn = FLT_MAX;
#pragma unroll
        for (int j = 0; j < 8; ++j) {
            dist[j] = sqrtf(fmaxf(dd[j], 1e-12f));
            dmn = fminf(dmn, dist[j]);
        }
        float w[8]; float s = 0.f;
#pragma unroll
        for (int j = 0; j < 8; ++j) { w[j] = expf(__fsub_rn(dmn, dist[j])); s += w[j]; }
        const int g = row * LONN + li;
#pragma unroll
        for (int j = 0; j < 8; ++j) {
            g_knw[g * 8 + j] = __fdiv_rn(w[j], s);
            g_kni[g * 8 + j] = xi[j];
        }
    }
}

// ---------------------------------------------------------------------------
// Gather + weighted combine + 64x64 linear + NCHW store (unchanged from R2).
// ---------------------------------------------------------------------------
__global__ __launch_bounds__(256) void gather_kernel(const float* __restrict__ M,
                                                     const float* __restrict__ W,
                                                     const float* __restrict__ bias,
                                                     float* __restrict__ out) {
    __shared__ float s_w[8][8];
    __shared__ int   s_i[8][8];
    __shared__ float s_W[64 * 65];                       // s_W[c*65+c'] = W[c'][c]
    __shared__ __align__(16) float s_it[BATCH * CH * 8]; // [b][c][g], pitch 8

    const int tid = threadIdx.x;
    const int g0  = blockIdx.x * 8;

    for (int i = tid; i < CH * CH; i += 256) {
        int cp = i >> 6;
        int c  = i & 63;
        s_W[c * 65 + cp] = W[i];
    }
    if (tid < 64) {
        int gg = tid >> 3, k = tid & 7;
        int g = g0 + gg;
        if (g < NG) { s_w[gg][k] = g_knw[g * 8 + k]; s_i[gg][k] = g_kni[g * 8 + k]; }
        else        { s_w[gg][k] = 0.f;              s_i[gg][k] = 0; }
    }
    __syncthreads();

    const int b = tid >> 6;
    const int c = tid & 63;

    const float* Mb = M + (size_t)b * NODES * CH + c;
    float r[8];
#pragma unroll
    for (int gg = 0; gg < 8; ++gg) {
        float a = 0.f;
#pragma unroll
        for (int k = 0; k < 8; ++k)
            a = __fmaf_rn(s_w[gg][k], Mb[(size_t)s_i[gg][k] * CH], a);
        r[gg] = a;
    }
    float* ip = &s_it[(b * CH + c) * 8];
    ((float4*)ip)[0] = make_float4(r[0], r[1], r[2], r[3]);
    ((float4*)ip)[1] = make_float4(r[4], r[5], r[6], r[7]);
    __syncthreads();

    float a[8];
    const float bv = bias[c];
#pragma unroll
    for (int gg = 0; gg < 8; ++gg) a[gg] = bv;
    const float* ib = &s_it[b * CH * 8];
#pragma unroll 8
    for (int cc = 0; cc < CH; ++cc) {
        float4 v0 = ((const float4*)(ib + cc * 8))[0];
        float4 v1 = ((const float4*)(ib + cc * 8))[1];
        float w = s_W[cc * 65 + c];
        a[0] = __fmaf_rn(w, v0.x, a[0]); a[1] = __fmaf_rn(w, v0.y, a[1]);
        a[2] = __fmaf_rn(w, v0.z, a[2]); a[3] = __fmaf_rn(w, v0.w, a[3]);
        a[4] = __fmaf_rn(w, v1.x, a[4]); a[5] = __fmaf_rn(w, v1.y, a[5]);
        a[6] = __fmaf_rn(w, v1.z, a[6]); a[7] = __fmaf_rn(w, v1.w, a[7]);
    }

    float* op = out + (size_t)(b * CH + c) * NG + g0;
    if (g0 + 8 <= NG) {
        ((float4*)op)[0] = make_float4(a[0], a[1], a[2], a[3]);
        ((float4*)op)[1] = make_float4(a[4], a[5], a[6], a[7]);
    } else {
#pragma unroll
        for (int gg = 0; gg < 8; ++gg)
            if (g0 + gg < NG) op[gg] = a[gg];
    }
}

// ---------------------------------------------------------------------------
extern "C" void kernel_launch(void* const* d_in, const int* in_sizes, int n_in,
                              void* d_out, int out_size) {
    const float* mesh_output   = (const float*)d_in[0];  // (4,10242,64)
    const float* mesh_vertices = (const float*)d_in[1];  // (10242,3)
    const float* lat           = (const float*)d_in[2];  // (91,)
    const float* lon           = (const float*)d_in[3];  // (180,)
    const float* W             = (const float*)d_in[4];  // (64,64)
    const float* bvec          = (const float*)d_in[5];  // (64,)
    float* out = (float*)d_out;                          // (4,64,91,180)

    zero_kernel<<<1, 128>>>();
    prep_hist_kernel<<<(NODES + 255) / 256, 256>>>(mesh_vertices);
    scan_kernel<<<1, 32>>>();
    scatter_kernel<<<(NODES + 255) / 256, 256>>>();
    knn_kernel<<<LATN * 2, KT>>>(lat, lon);
    gather_kernel<<<(NG + 7) / 8, 256>>>(mesh_output, W, bvec, out);
}